// round 13
// baseline (speedup 1.0000x reference)
#include <cuda_runtime.h>
#include <cuda_fp16.h>
#include <cstdint>
#include <mma.h>

using namespace nvcuda;

#define Bv 4
#define CIN 256
#define HW 65536
#define Lv 5000
#define DLOI 128
#define DFC 1024
#define NOUT 2500
#define NLINES (Bv*Lv)
#define NPAD 20096            // 157 * 128 row tiles
#define NROWT (NPAD / 128)    // 157
#define NT (NROWT * (DFC / 128))   // 1256 tiles per gemm

// ---------------- scratch (static __device__, no allocs) ----------------
__device__ float  g_x[(size_t)Bv * HW * DLOI];
__device__ __half g_flath[(size_t)NPAD * DFC];
__device__ __half g_flatl[(size_t)NPAD * DFC];
__device__ __half g_h1h[(size_t)NPAD * DFC];
__device__ __half g_h1l[(size_t)NPAD * DFC];
__device__ float  g_h2[(size_t)NPAD * DFC];
__device__ __half g_w1h[DFC * DFC];
__device__ __half g_w1l[DFC * DFC];
__device__ __half g_w2h[DFC * DFC];
__device__ __half g_w2l[DFC * DFC];
__device__ __half g_cwh[DLOI * CIN];
__device__ __half g_cwl[DLOI * CIN];
__device__ int    g_rowdone[NROWT];
__device__ float  g_s[NLINES * 4];
__device__ int    g_key[NLINES];
__device__ int    g_order[NLINES];

__device__ __forceinline__ uint32_t smem_u32(const void* p) {
    uint32_t a;
    asm("{ .reg .u64 t; cvta.to.shared.u64 t, %1; cvt.u32.u64 %0, t; }" : "=r"(a) : "l"(p));
    return a;
}
__device__ __forceinline__ void cp_async16(uint32_t dst, const void* src) {
    asm volatile("cp.async.cg.shared.global [%0], [%1], 16;" :: "r"(dst), "l"(src));
}
#define CP_COMMIT() asm volatile("cp.async.commit_group;" ::: "memory")
#define CP_WAIT1()  asm volatile("cp.async.wait_group 1;" ::: "memory")
#define CP_WAIT0()  asm volatile("cp.async.wait_group 0;" ::: "memory")

__device__ __forceinline__ void split_h(float v, __half& h, __half& l) {
    h = __float2half_rn(v);
    l = __float2half_rn(v - __half2float(h));
}
__device__ __forceinline__ void split4_to(const float4 v, __half* h, __half* l) {
    split_h(v.x, h[0], l[0]); split_h(v.y, h[1], l[1]);
    split_h(v.z, h[2], l[2]); split_h(v.w, h[3], l[3]);
}

// ---------------- K0: split w1/w2/fc1_w into hi/lo; block 0 zeros g_rowdone
#define W1F4 (DFC * DFC / 4)
#define CWF4 (DLOI * CIN / 4)
__global__ __launch_bounds__(256) void split_w_kernel(const float* __restrict__ w1,
                                                      const float* __restrict__ w2,
                                                      const float* __restrict__ cw) {
    if (blockIdx.x == 0 && threadIdx.x < NROWT) g_rowdone[threadIdx.x] = 0;
    const int i4 = blockIdx.x * blockDim.x + threadIdx.x;
    __half h[4], l[4];
    if (i4 < W1F4) {
        split4_to(*(const float4*)&w1[(size_t)i4 * 4], h, l);
        *(uint2*)&g_w1h[(size_t)i4 * 4] = *(uint2*)h;
        *(uint2*)&g_w1l[(size_t)i4 * 4] = *(uint2*)l;
    } else if (i4 < 2 * W1F4) {
        int j = i4 - W1F4;
        split4_to(*(const float4*)&w2[(size_t)j * 4], h, l);
        *(uint2*)&g_w2h[(size_t)j * 4] = *(uint2*)h;
        *(uint2*)&g_w2l[(size_t)j * 4] = *(uint2*)l;
    } else if (i4 < 2 * W1F4 + CWF4) {
        int j = i4 - 2 * W1F4;
        split4_to(*(const float4*)&cw[(size_t)j * 4], h, l);
        *(uint2*)&g_cwh[(size_t)j * 4] = *(uint2*)h;
        *(uint2*)&g_cwl[(size_t)j * 4] = *(uint2*)l;
    }
}

// ---------------- K1: conv1x1 fp16x3 wmma, fused f32->hi/lo split in the loader
#define CLA 136
#define CLB 40
#define CAT (32 * CLA)
#define CBT (128 * CLB)
#define CSTG (2 * (CAT + CBT))
#define CC_SMEM (2 * CSTG * 2)
#define STG_LD 20

__global__ __launch_bounds__(256, 2) void conv_wmma_kernel(const float* __restrict__ feat,
                                                           const float* __restrict__ bias) {
    extern __shared__ __half cmem[];
    const uint32_t sb = smem_u32(cmem);
    const int tid = threadIdx.x;
    const int wid = tid >> 5, lane = tid & 31;
    const int wm = wid & 3, wn = wid >> 2;
    const int b = blockIdx.y;
    const int p0 = blockIdx.x * 128;

    wmma::fragment<wmma::accumulator, 16, 16, 16, float> acc[2][4];
#pragma unroll
    for (int mi = 0; mi < 2; mi++)
#pragma unroll
        for (int ni = 0; ni < 4; ni++) wmma::fill_fragment(acc[mi][ni], 0.f);

    float4 cur[4];
    auto ldgA = [&](int c0) {
#pragma unroll
        for (int r = 0; r < 4; r++) {
            int slot = tid + r * 256;
            int k = slot >> 5, c4 = slot & 31;
            cur[r] = *(const float4*)&feat[((size_t)b * CIN + c0 + k) * HW + p0 + c4 * 4];
        }
    };
    auto stsA = [&](int s) {
#pragma unroll
        for (int r = 0; r < 4; r++) {
            int slot = tid + r * 256;
            int k = slot >> 5, c4 = slot & 31;
            __half h[4], l[4];
            split4_to(cur[r], h, l);
            __half* base = cmem + s * CSTG + k * CLA + c4 * 4;
            *(uint2*)base = *(uint2*)h;
            *(uint2*)(base + CAT) = *(uint2*)l;
        }
    };
    auto cpB = [&](int s, int c0) {
#pragma unroll
        for (int r = 0; r < 2; r++) {
            int slot = tid + r * 256;
            int n = slot >> 2, ch = slot & 3;
            size_t gw = (size_t)n * CIN + c0 + ch * 8;
            uint32_t so = (uint32_t)((s * CSTG + 2 * CAT + n * CLB + ch * 8) * 2);
            cp_async16(sb + so, &g_cwh[gw]);
            cp_async16(sb + so + CBT * 2, &g_cwl[gw]);
        }
    };

    ldgA(0);
    cpB(0, 0);
    CP_COMMIT();

    const int nk = CIN / 32;
    for (int i = 0; i < nk; i++) {
        const int s = i & 1;
        stsA(s);
        if (i + 1 < nk) ldgA((i + 1) * 32);
        CP_WAIT0();
        __syncthreads();
        if (i + 1 < nk) { cpB(s ^ 1, (i + 1) * 32); CP_COMMIT(); }

        const __half* sAh = cmem + s * CSTG;
        const __half* sAl = sAh + CAT;
        const __half* sBh = sAh + 2 * CAT;
        const __half* sBl = sBh + CBT;
#pragma unroll
        for (int kk = 0; kk < 32; kk += 16) {
            // pass-staged: hh, lh (share fbh), then hl — breaks acc RAW chains
            wmma::fragment<wmma::matrix_a, 16, 16, 16, __half, wmma::col_major> fah[2], fal[2];
            wmma::fragment<wmma::matrix_b, 16, 16, 16, __half, wmma::col_major> fbh[4], fbl[4];
#pragma unroll
            for (int mi = 0; mi < 2; mi++) {
                const int m0 = wm * 32 + mi * 16;
                wmma::load_matrix_sync(fah[mi], sAh + kk * CLA + m0, CLA);
                wmma::load_matrix_sync(fal[mi], sAl + kk * CLA + m0, CLA);
            }
#pragma unroll
            for (int ni = 0; ni < 4; ni++)
                wmma::load_matrix_sync(fbh[ni], sBh + (wn * 64 + ni * 16) * CLB + kk, CLB);
#pragma unroll
            for (int ni = 0; ni < 4; ni++)
#pragma unroll
                for (int mi = 0; mi < 2; mi++)
                    wmma::mma_sync(acc[mi][ni], fah[mi], fbh[ni], acc[mi][ni]);
#pragma unroll
            for (int ni = 0; ni < 4; ni++)
#pragma unroll
                for (int mi = 0; mi < 2; mi++)
                    wmma::mma_sync(acc[mi][ni], fal[mi], fbh[ni], acc[mi][ni]);
#pragma unroll
            for (int ni = 0; ni < 4; ni++)
                wmma::load_matrix_sync(fbl[ni], sBl + (wn * 64 + ni * 16) * CLB + kk, CLB);
#pragma unroll
            for (int ni = 0; ni < 4; ni++)
#pragma unroll
                for (int mi = 0; mi < 2; mi++)
                    wmma::mma_sync(acc[mi][ni], fah[mi], fbl[ni], acc[mi][ni]);
        }
        __syncthreads();
    }

    float* stg = (float*)cmem + wid * (16 * STG_LD);
    const int er = lane >> 1;
    const int ec = (lane & 1) * 8;
    float* xb = g_x + (size_t)b * HW * DLOI;
#pragma unroll
    for (int mi = 0; mi < 2; mi++)
#pragma unroll
        for (int ni = 0; ni < 4; ni++) {
            wmma::store_matrix_sync(stg, acc[mi][ni], STG_LD, wmma::mem_row_major);
            __syncwarp();
            const int gp = p0 + wm * 32 + mi * 16 + er;
            const int go = wn * 64 + ni * 16 + ec;
            const float* sp = stg + er * STG_LD + ec;
            const float* bp = bias + go;
            *(float4*)&xb[(size_t)gp * DLOI + go] =
                make_float4(sp[0] + bp[0], sp[1] + bp[1], sp[2] + bp[2], sp[3] + bp[3]);
            *(float4*)&xb[(size_t)gp * DLOI + go + 4] =
                make_float4(sp[4] + bp[4], sp[5] + bp[5], sp[6] + bp[6], sp[7] + bp[7]);
            __syncwarp();
        }
}

// ---------------- K2: cooperative sampler
__global__ __launch_bounds__(128) void sample_pool_kernel(const float* __restrict__ lines) {
    const int b = blockIdx.y, l = blockIdx.x, c = threadIdx.x;
    __shared__ int4   s_o[32];
    __shared__ float4 s_wt[32];
    __shared__ float  buf[DFC];

    if (c < 32) {
        const float* ln = lines + ((size_t)b * Lv + l) * 4;
        float lam = (1.0f / 31.0f) * (float)c;
        float px = ln[0] * lam + ln[2] * (1.f - lam) - 0.5f;
        float py = ln[1] * lam + ln[3] * (1.f - lam) - 0.5f;
        float px0 = fminf(fmaxf(floorf(px), 0.f), 255.f);
        float py0 = fminf(fmaxf(floorf(py), 0.f), 255.f);
        float px1 = fminf(px0 + 1.f, 255.f);
        float py1 = fminf(py0 + 1.f, 255.f);
        int ix0 = (int)px0, iy0 = (int)py0, ix1 = (int)px1, iy1 = (int)py1;
        s_o[c] = make_int4((ix0 * 256 + iy0) * DLOI, (ix1 * 256 + iy0) * DLOI,
                           (ix0 * 256 + iy1) * DLOI, (ix1 * 256 + iy1) * DLOI);
        s_wt[c] = make_float4((px1 - px) * (py1 - py), (px - px0) * (py1 - py),
                              (px1 - px) * (py - py0), (px - px0) * (py - py0));
    }
    __syncthreads();

    const float* xb = g_x + (size_t)b * HW * DLOI;
    float m = -3.402823466e38f;
#pragma unroll
    for (int j = 0; j < 32; j++) {
        int4 o = s_o[j];
        float4 w = s_wt[j];
        float v = xb[o.x + c] * w.x;
        v = fmaf(xb[o.y + c], w.y, v);
        v = fmaf(xb[o.z + c], w.z, v);
        v = fmaf(xb[o.w + c], w.w, v);
        m = fmaxf(m, v);
        if ((j & 3) == 3) {
            buf[c * 8 + (j >> 2)] = m;
            m = -3.402823466e38f;
        }
    }
    __syncthreads();
    const size_t row = (size_t)b * Lv + l;
    const float* bp = buf + c * 8;
    __half h[8], lo[8];
#pragma unroll
    for (int j = 0; j < 8; j++) split_h(bp[j], h[j], lo[j]);
    *(uint4*)&g_flath[row * DFC + c * 8] = *(uint4*)h;
    *(uint4*)&g_flatl[row * DFC + c * 8] = *(uint4*)lo;
}

// ---------------- persistent fused dual-GEMM (fp16x3), 4 warps of 64x64
#define LDH 40
#define HT (128 * LDH)
#define GH_SMEM (8 * HT * 2)

__global__ __launch_bounds__(128, 2) void gemm_fused_kernel(const float* __restrict__ b1,
                                                            const float* __restrict__ b2) {
    extern __shared__ __half hmem[];
    const uint32_t sb = smem_u32(hmem);
    const int tid = threadIdx.x;
    const int wid = tid >> 5, lane = tid & 31;
    const int wm = wid & 1, wn = wid >> 1;
    const int lrow = tid >> 2, lchunk = tid & 3;

    for (int t = blockIdx.x; t < 2 * NT; t += gridDim.x) {
        const int isg1 = (t < NT);
        const int u = isg1 ? t : t - NT;
        const int row = u >> 3, col = u & 7;
        const __half *Ah, *Al, *Wh, *Wl;
        const float* bias;
        if (isg1) {
            Ah = g_flath; Al = g_flatl; Wh = g_w1h; Wl = g_w1l; bias = b1;
        } else {
            if (tid == 0) {
                volatile int* rd = &g_rowdone[row];
                while (*rd < 8) __nanosleep(64);
            }
            __syncthreads();
            __threadfence();
            Ah = g_h1h; Al = g_h1l; Wh = g_w2h; Wl = g_w2l; bias = b2;
        }
        const int rowbase = row * 128;
        const int colbase = col * 128;

        wmma::fragment<wmma::accumulator, 16, 16, 16, float> acc[4][4];
#pragma unroll
        for (int mi = 0; mi < 4; mi++)
#pragma unroll
            for (int ni = 0; ni < 4; ni++) wmma::fill_fragment(acc[mi][ni], 0.f);

        auto load_stage = [&](int s, int k0) {
#pragma unroll
            for (int r = 0; r < 4; r++) {
                const int rr = lrow + r * 32;
                const uint32_t so = (uint32_t)((s * 4 * HT + rr * LDH + lchunk * 8) * 2);
                const size_t ga = (size_t)(rowbase + rr) * DFC + k0 + lchunk * 8;
                const size_t gb = (size_t)(colbase + rr) * DFC + k0 + lchunk * 8;
                cp_async16(sb + so,              &Ah[ga]);
                cp_async16(sb + so + HT * 2,     &Al[ga]);
                cp_async16(sb + so + 2 * HT * 2, &Wh[gb]);
                cp_async16(sb + so + 3 * HT * 2, &Wl[gb]);
            }
        };

        load_stage(0, 0);
        CP_COMMIT();

        const int nk = DFC / 32;
        for (int i = 0; i < nk; i++) {
            const int s = i & 1;
            if (i + 1 < nk) {
                load_stage(s ^ 1, (i + 1) * 32);
                CP_COMMIT();
                CP_WAIT1();
            } else {
                CP_WAIT0();
            }
            __syncthreads();

            const __half* sAh = hmem + s * 4 * HT;
            const __half* sAl = sAh + HT;
            const __half* sBh = sAh + 2 * HT;
            const __half* sBl = sAh + 3 * HT;
#pragma unroll
            for (int kk = 0; kk < 32; kk += 16) {
                // load all fragments, then 3 passes of 16 independent MMAs each
                wmma::fragment<wmma::matrix_a, 16, 16, 16, __half, wmma::row_major> fah[4], fal[4];
                wmma::fragment<wmma::matrix_b, 16, 16, 16, __half, wmma::col_major> fbh[4], fbl[4];
#pragma unroll
                for (int mi = 0; mi < 4; mi++) {
                    const int m0 = wm * 64 + mi * 16;
                    wmma::load_matrix_sync(fah[mi], sAh + m0 * LDH + kk, LDH);
                    wmma::load_matrix_sync(fal[mi], sAl + m0 * LDH + kk, LDH);
                }
#pragma unroll
                for (int ni = 0; ni < 4; ni++) {
                    const int n0 = wn * 64 + ni * 16;
                    wmma::load_matrix_sync(fbh[ni], sBh + n0 * LDH + kk, LDH);
                    wmma::load_matrix_sync(fbl[ni], sBl + n0 * LDH + kk, LDH);
                }
#pragma unroll
                for (int mi = 0; mi < 4; mi++)
#pragma unroll
                    for (int ni = 0; ni < 4; ni++)
                        wmma::mma_sync(acc[mi][ni], fah[mi], fbh[ni], acc[mi][ni]);
#pragma unroll
                for (int mi = 0; mi < 4; mi++)
#pragma unroll
                    for (int ni = 0; ni < 4; ni++)
                        wmma::mma_sync(acc[mi][ni], fal[mi], fbh[ni], acc[mi][ni]);
#pragma unroll
                for (int mi = 0; mi < 4; mi++)
#pragma unroll
                    for (int ni = 0; ni < 4; ni++)
                        wmma::mma_sync(acc[mi][ni], fah[mi], fbl[ni], acc[mi][ni]);
            }
            __syncthreads();
        }

        float* stg = (float*)hmem + wid * (16 * STG_LD);
        const int er = lane >> 1;
        const int ec = (lane & 1) * 8;
#pragma unroll
        for (int mi = 0; mi < 4; mi++)
#pragma unroll
            for (int ni = 0; ni < 4; ni++) {
                wmma::store_matrix_sync(stg, acc[mi][ni], STG_LD, wmma::mem_row_major);
                __syncwarp();
                const int gr = rowbase + wm * 64 + mi * 16 + er;
                const int gc = colbase + wn * 64 + ni * 16 + ec;
                const float* sp = stg + er * STG_LD + ec;
                const float* bp = bias + gc;
                float r[8];
#pragma unroll
                for (int j = 0; j < 8; j++) r[j] = fmaxf(sp[j] + bp[j], 0.f);
                if (isg1) {
                    __half h[8], lo[8];
#pragma unroll
                    for (int j = 0; j < 8; j++) split_h(r[j], h[j], lo[j]);
                    *(uint4*)&g_h1h[(size_t)gr * DFC + gc] = *(uint4*)h;
                    *(uint4*)&g_h1l[(size_t)gr * DFC + gc] = *(uint4*)lo;
                } else {
                    *(float4*)&g_h2[(size_t)gr * DFC + gc] = make_float4(r[0], r[1], r[2], r[3]);
                    *(float4*)&g_h2[(size_t)gr * DFC + gc + 4] = make_float4(r[4], r[5], r[6], r[7]);
                }
                __syncwarp();
            }

        __threadfence();
        __syncthreads();
        if (isg1 && tid == 0) atomicAdd(&g_rowdone[row], 1);
    }
}

// ---------------- K5: logits -> softmax -> mask/key (warp per line)
__global__ __launch_bounds__(256) void head_kernel(const float* __restrict__ w3,
                                                   const float* __restrict__ b3) {
    const int line = blockIdx.x * 8 + (threadIdx.x >> 5);
    if (line >= NLINES) return;
    const int lane = threadIdx.x & 31;
    const float4* hr = (const float4*)(g_h2 + (size_t)line * DFC);
    const float4* wr0 = (const float4*)(w3);
    const float4* wr1 = (const float4*)(w3 + DFC);
    const float4* wr2 = (const float4*)(w3 + 2 * DFC);
    const float4* wr3 = (const float4*)(w3 + 3 * DFC);
    float a0 = 0.f, a1 = 0.f, a2 = 0.f, a3 = 0.f;
    for (int k = lane; k < 256; k += 32) {
        float4 h = hr[k];
        float4 x;
        x = wr0[k]; a0 += h.x * x.x + h.y * x.y + h.z * x.z + h.w * x.w;
        x = wr1[k]; a1 += h.x * x.x + h.y * x.y + h.z * x.z + h.w * x.w;
        x = wr2[k]; a2 += h.x * x.x + h.y * x.y + h.z * x.z + h.w * x.w;
        x = wr3[k]; a3 += h.x * x.x + h.y * x.y + h.z * x.z + h.w * x.w;
    }
#pragma unroll
    for (int d = 16; d > 0; d >>= 1) {
        a0 += __shfl_xor_sync(0xffffffffu, a0, d);
        a1 += __shfl_xor_sync(0xffffffffu, a1, d);
        a2 += __shfl_xor_sync(0xffffffffu, a2, d);
        a3 += __shfl_xor_sync(0xffffffffu, a3, d);
    }
    if (lane == 0) {
        float l0 = a0 + b3[0], l1 = a1 + b3[1], l2 = a2 + b3[2], l3 = a3 + b3[3];
        float mx = fmaxf(fmaxf(l0, l1), fmaxf(l2, l3));
        float e0 = expf(l0 - mx), e1 = expf(l1 - mx), e2 = expf(l2 - mx), e3 = expf(l3 - mx);
        float inv = 1.f / (e0 + e1 + e2 + e3);
        float s0 = e0 * inv, s1 = e1 * inv, s2 = e2 * inv, s3 = e3 * inv;
        int am = 0; float bm = l0;
        if (l1 > bm) { am = 1; bm = l1; }
        if (l2 > bm) { am = 2; bm = l2; }
        if (l3 > bm) { am = 3; bm = l3; }
        bool mask = (s1 > 0.25f || s2 > 0.25f || s3 > 0.25f) && (s0 < 0.25f);
        *(float4*)&g_s[line * 4] = make_float4(s0, s1, s2, s3);
        g_key[line] = mask ? am : -1;
    }
}

// ---------------- K6: per-batch stable counting sort + cyclic gather to output
__global__ __launch_bounds__(1024) void select_kernel(const float* __restrict__ lines,
                                                      float* __restrict__ out) {
    const int b = blockIdx.x;
    const int tid = threadIdx.x;
    const int lane = tid & 31, wid = tid >> 5;
    __shared__ int warp_sums[32];
    __shared__ int s_base;
    if (tid == 0) s_base = 0;
    const int* keyb = g_key + b * Lv;
    int* ordb = g_order + b * Lv;

    for (int kv = 3; kv >= 0; kv--) {
        for (int chunk = 0; chunk < Lv; chunk += 1024) {
            __syncthreads();
            int i = chunk + tid;
            int pred = (i < Lv && keyb[i] == kv) ? 1 : 0;
            int incl = pred;
#pragma unroll
            for (int d = 1; d < 32; d <<= 1) {
                int v = __shfl_up_sync(0xffffffffu, incl, d);
                if (lane >= d) incl += v;
            }
            if (lane == 31) warp_sums[wid] = incl;
            __syncthreads();
            if (wid == 0) {
                int inc2 = warp_sums[lane];
#pragma unroll
                for (int d = 1; d < 32; d <<= 1) {
                    int t = __shfl_up_sync(0xffffffffu, inc2, d);
                    if (lane >= d) inc2 += t;
                }
                warp_sums[lane] = inc2;
            }
            __syncthreads();
            int excl = incl - pred + (wid > 0 ? warp_sums[wid - 1] : 0);
            int total = warp_sums[31];
            int base = s_base;
            if (pred) ordb[base + excl] = i;
            __syncthreads();
            if (tid == 0) s_base = base + total;
        }
    }
    __syncthreads();
    const int cnt = s_base;

    float* out_lines = out + (size_t)b * NOUT * 4;
    float* out_scores = out + (size_t)Bv * NOUT * 4 + (size_t)b * NOUT * 4;
    for (int i = tid; i < NOUT; i += 1024) {
        float4 lv = make_float4(0.f, 0.f, 0.f, 0.f);
        float4 sv = make_float4(0.f, 0.f, 0.f, 0.f);
        if (cnt > 0) {
            int sel = ordb[i % cnt];
            lv = *(const float4*)&lines[((size_t)b * Lv + sel) * 4];
            sv = *(const float4*)&g_s[(b * Lv + sel) * 4];
        }
        *(float4*)&out_lines[(size_t)i * 4] = lv;
        *(float4*)&out_scores[(size_t)i * 4] = sv;
    }
}

// ---------------- launch ----------------
extern "C" void kernel_launch(void* const* d_in, const int* in_sizes, int n_in,
                              void* d_out, int out_size) {
    const float* feature = (const float*)d_in[0];
    const float* lines   = (const float*)d_in[1];
    const float* fc1_w   = (const float*)d_in[2];
    const float* fc1_b   = (const float*)d_in[3];
    const float* w1      = (const float*)d_in[4];
    const float* b1      = (const float*)d_in[5];
    const float* w2      = (const float*)d_in[6];
    const float* b2      = (const float*)d_in[7];
    const float* w3      = (const float*)d_in[8];
    const float* b3      = (const float*)d_in[9];
    float* out = (float*)d_out;

    cudaFuncSetAttribute(gemm_fused_kernel, cudaFuncAttributeMaxDynamicSharedMemorySize, GH_SMEM);
    cudaFuncSetAttribute(conv_wmma_kernel, cudaFuncAttributeMaxDynamicSharedMemorySize, CC_SMEM);

    int dev = 0;
    cudaGetDevice(&dev);
    int nsm = 0;
    cudaDeviceGetAttribute(&nsm, cudaDevAttrMultiProcessorCount, dev);
    int nblk = 0;
    cudaOccupancyMaxActiveBlocksPerMultiprocessor(&nblk, gemm_fused_kernel, 128, GH_SMEM);
    if (nblk < 1) nblk = 1;
    int grid = nsm * nblk;
    if (grid > 2 * NT) grid = 2 * NT;

    split_w_kernel<<<(2 * W1F4 + CWF4 + 255) / 256, 256>>>(w1, w2, fc1_w);
    conv_wmma_kernel<<<dim3(HW / 128, Bv), 256, CC_SMEM>>>(feature, fc1_b);
    sample_pool_kernel<<<dim3(Lv, Bv), 128>>>(lines);
    gemm_fused_kernel<<<grid, 128, GH_SMEM>>>(b1, b2);
    head_kernel<<<(NLINES + 7) / 8, 256>>>(w3, b3);
    select_kernel<<<Bv, 1024>>>(lines, out);
}

// round 14
// speedup vs baseline: 1.0144x; 1.0144x over previous
#include <cuda_runtime.h>
#include <cuda_fp16.h>
#include <cstdint>
#include <mma.h>

using namespace nvcuda;

#define Bv 4
#define CIN 256
#define HW 65536
#define Lv 5000
#define DLOI 128
#define DFC 1024
#define NOUT 2500
#define NLINES (Bv*Lv)
#define NPAD 20096            // 157 * 128 row tiles
#define NROWT (NPAD / 128)    // 157
#define NT (NROWT * (DFC / 128))   // 1256 tiles per gemm

// ---------------- scratch (static __device__, no allocs) ----------------
__device__ float  g_x[(size_t)Bv * HW * DLOI];
__device__ __half g_flath[(size_t)NPAD * DFC];
__device__ __half g_flatl[(size_t)NPAD * DFC];
__device__ __half g_h1h[(size_t)NPAD * DFC];
__device__ __half g_h1l[(size_t)NPAD * DFC];
__device__ float  g_h2[(size_t)NPAD * DFC];
__device__ __half g_w1h[DFC * DFC];
__device__ __half g_w1l[DFC * DFC];
__device__ __half g_w2h[DFC * DFC];
__device__ __half g_w2l[DFC * DFC];
__device__ __half g_cwh[DLOI * CIN];
__device__ __half g_cwl[DLOI * CIN];
__device__ int    g_rowdone[NROWT];
__device__ float  g_s[NLINES * 4];
__device__ int    g_key[NLINES];
__device__ int    g_order[NLINES];

__device__ __forceinline__ uint32_t smem_u32(const void* p) {
    uint32_t a;
    asm("{ .reg .u64 t; cvta.to.shared.u64 t, %1; cvt.u32.u64 %0, t; }" : "=r"(a) : "l"(p));
    return a;
}
__device__ __forceinline__ void cp_async16(uint32_t dst, const void* src) {
    asm volatile("cp.async.cg.shared.global [%0], [%1], 16;" :: "r"(dst), "l"(src));
}
#define CP_COMMIT() asm volatile("cp.async.commit_group;" ::: "memory")
#define CP_WAIT1()  asm volatile("cp.async.wait_group 1;" ::: "memory")
#define CP_WAIT0()  asm volatile("cp.async.wait_group 0;" ::: "memory")

__device__ __forceinline__ void split_h(float v, __half& h, __half& l) {
    h = __float2half_rn(v);
    l = __float2half_rn(v - __half2float(h));
}
__device__ __forceinline__ void split4_to(const float4 v, __half* h, __half* l) {
    split_h(v.x, h[0], l[0]); split_h(v.y, h[1], l[1]);
    split_h(v.z, h[2], l[2]); split_h(v.w, h[3], l[3]);
}

// ---------------- K0: split w1/w2/fc1_w into hi/lo; block 0 zeros g_rowdone
#define W1F4 (DFC * DFC / 4)
#define CWF4 (DLOI * CIN / 4)
__global__ __launch_bounds__(256) void split_w_kernel(const float* __restrict__ w1,
                                                      const float* __restrict__ w2,
                                                      const float* __restrict__ cw) {
    if (blockIdx.x == 0 && threadIdx.x < NROWT) g_rowdone[threadIdx.x] = 0;
    const int i4 = blockIdx.x * blockDim.x + threadIdx.x;
    __half h[4], l[4];
    if (i4 < W1F4) {
        split4_to(*(const float4*)&w1[(size_t)i4 * 4], h, l);
        *(uint2*)&g_w1h[(size_t)i4 * 4] = *(uint2*)h;
        *(uint2*)&g_w1l[(size_t)i4 * 4] = *(uint2*)l;
    } else if (i4 < 2 * W1F4) {
        int j = i4 - W1F4;
        split4_to(*(const float4*)&w2[(size_t)j * 4], h, l);
        *(uint2*)&g_w2h[(size_t)j * 4] = *(uint2*)h;
        *(uint2*)&g_w2l[(size_t)j * 4] = *(uint2*)l;
    } else if (i4 < 2 * W1F4 + CWF4) {
        int j = i4 - 2 * W1F4;
        split4_to(*(const float4*)&cw[(size_t)j * 4], h, l);
        *(uint2*)&g_cwh[(size_t)j * 4] = *(uint2*)h;
        *(uint2*)&g_cwl[(size_t)j * 4] = *(uint2*)l;
    }
}

// ---------------- K1: conv1x1 fp16x3 wmma (R12 form), fused f32->hi/lo split loader
#define CLA 136
#define CLB 40
#define CAT (32 * CLA)
#define CBT (128 * CLB)
#define CSTG (2 * (CAT + CBT))
#define CC_SMEM (2 * CSTG * 2)
#define STG_LD 20

__global__ __launch_bounds__(256, 2) void conv_wmma_kernel(const float* __restrict__ feat,
                                                           const float* __restrict__ bias) {
    extern __shared__ __half cmem[];
    const uint32_t sb = smem_u32(cmem);
    const int tid = threadIdx.x;
    const int wid = tid >> 5, lane = tid & 31;
    const int wm = wid & 3, wn = wid >> 2;
    const int b = blockIdx.y;
    const int p0 = blockIdx.x * 128;

    wmma::fragment<wmma::accumulator, 16, 16, 16, float> acc[2][4];
#pragma unroll
    for (int mi = 0; mi < 2; mi++)
#pragma unroll
        for (int ni = 0; ni < 4; ni++) wmma::fill_fragment(acc[mi][ni], 0.f);

    float4 cur[4];
    auto ldgA = [&](int c0) {
#pragma unroll
        for (int r = 0; r < 4; r++) {
            int slot = tid + r * 256;
            int k = slot >> 5, c4 = slot & 31;
            cur[r] = *(const float4*)&feat[((size_t)b * CIN + c0 + k) * HW + p0 + c4 * 4];
        }
    };
    auto stsA = [&](int s) {
#pragma unroll
        for (int r = 0; r < 4; r++) {
            int slot = tid + r * 256;
            int k = slot >> 5, c4 = slot & 31;
            __half h[4], l[4];
            split4_to(cur[r], h, l);
            __half* base = cmem + s * CSTG + k * CLA + c4 * 4;
            *(uint2*)base = *(uint2*)h;
            *(uint2*)(base + CAT) = *(uint2*)l;
        }
    };
    auto cpB = [&](int s, int c0) {
#pragma unroll
        for (int r = 0; r < 2; r++) {
            int slot = tid + r * 256;
            int n = slot >> 2, ch = slot & 3;
            size_t gw = (size_t)n * CIN + c0 + ch * 8;
            uint32_t so = (uint32_t)((s * CSTG + 2 * CAT + n * CLB + ch * 8) * 2);
            cp_async16(sb + so, &g_cwh[gw]);
            cp_async16(sb + so + CBT * 2, &g_cwl[gw]);
        }
    };

    ldgA(0);
    cpB(0, 0);
    CP_COMMIT();

    const int nk = CIN / 32;
    for (int i = 0; i < nk; i++) {
        const int s = i & 1;
        stsA(s);
        if (i + 1 < nk) ldgA((i + 1) * 32);
        CP_WAIT0();
        __syncthreads();
        if (i + 1 < nk) { cpB(s ^ 1, (i + 1) * 32); CP_COMMIT(); }

        const __half* sAh = cmem + s * CSTG;
        const __half* sAl = sAh + CAT;
        const __half* sBh = sAh + 2 * CAT;
        const __half* sBl = sBh + CBT;
#pragma unroll
        for (int kk = 0; kk < 32; kk += 16) {
            wmma::fragment<wmma::matrix_a, 16, 16, 16, __half, wmma::col_major> fah[2], fal[2];
#pragma unroll
            for (int mi = 0; mi < 2; mi++) {
                const int m0 = wm * 32 + mi * 16;
                wmma::load_matrix_sync(fah[mi], sAh + kk * CLA + m0, CLA);
                wmma::load_matrix_sync(fal[mi], sAl + kk * CLA + m0, CLA);
            }
#pragma unroll
            for (int ni = 0; ni < 4; ni++) {
                const int n0 = wn * 64 + ni * 16;
                wmma::fragment<wmma::matrix_b, 16, 16, 16, __half, wmma::col_major> fbh, fbl;
                wmma::load_matrix_sync(fbh, sBh + n0 * CLB + kk, CLB);
                wmma::load_matrix_sync(fbl, sBl + n0 * CLB + kk, CLB);
#pragma unroll
                for (int mi = 0; mi < 2; mi++) {
                    wmma::mma_sync(acc[mi][ni], fah[mi], fbh, acc[mi][ni]);
                    wmma::mma_sync(acc[mi][ni], fah[mi], fbl, acc[mi][ni]);
                    wmma::mma_sync(acc[mi][ni], fal[mi], fbh, acc[mi][ni]);
                }
            }
        }
        __syncthreads();
    }

    float* stg = (float*)cmem + wid * (16 * STG_LD);
    const int er = lane >> 1;
    const int ec = (lane & 1) * 8;
    float* xb = g_x + (size_t)b * HW * DLOI;
#pragma unroll
    for (int mi = 0; mi < 2; mi++)
#pragma unroll
        for (int ni = 0; ni < 4; ni++) {
            wmma::store_matrix_sync(stg, acc[mi][ni], STG_LD, wmma::mem_row_major);
            __syncwarp();
            const int gp = p0 + wm * 32 + mi * 16 + er;
            const int go = wn * 64 + ni * 16 + ec;
            const float* sp = stg + er * STG_LD + ec;
            const float* bp = bias + go;
            *(float4*)&xb[(size_t)gp * DLOI + go] =
                make_float4(sp[0] + bp[0], sp[1] + bp[1], sp[2] + bp[2], sp[3] + bp[3]);
            *(float4*)&xb[(size_t)gp * DLOI + go + 4] =
                make_float4(sp[4] + bp[4], sp[5] + bp[5], sp[6] + bp[6], sp[7] + bp[7]);
            __syncwarp();
        }
}

// ---------------- K2: cooperative sampler
__global__ __launch_bounds__(128) void sample_pool_kernel(const float* __restrict__ lines) {
    const int b = blockIdx.y, l = blockIdx.x, c = threadIdx.x;
    __shared__ int4   s_o[32];
    __shared__ float4 s_wt[32];
    __shared__ float  buf[DFC];

    if (c < 32) {
        const float* ln = lines + ((size_t)b * Lv + l) * 4;
        float lam = (1.0f / 31.0f) * (float)c;
        float px = ln[0] * lam + ln[2] * (1.f - lam) - 0.5f;
        float py = ln[1] * lam + ln[3] * (1.f - lam) - 0.5f;
        float px0 = fminf(fmaxf(floorf(px), 0.f), 255.f);
        float py0 = fminf(fmaxf(floorf(py), 0.f), 255.f);
        float px1 = fminf(px0 + 1.f, 255.f);
        float py1 = fminf(py0 + 1.f, 255.f);
        int ix0 = (int)px0, iy0 = (int)py0, ix1 = (int)px1, iy1 = (int)py1;
        s_o[c] = make_int4((ix0 * 256 + iy0) * DLOI, (ix1 * 256 + iy0) * DLOI,
                           (ix0 * 256 + iy1) * DLOI, (ix1 * 256 + iy1) * DLOI);
        s_wt[c] = make_float4((px1 - px) * (py1 - py), (px - px0) * (py1 - py),
                              (px1 - px) * (py - py0), (px - px0) * (py - py0));
    }
    __syncthreads();

    const float* xb = g_x + (size_t)b * HW * DLOI;
    float m = -3.402823466e38f;
#pragma unroll
    for (int j = 0; j < 32; j++) {
        int4 o = s_o[j];
        float4 w = s_wt[j];
        float v = xb[o.x + c] * w.x;
        v = fmaf(xb[o.y + c], w.y, v);
        v = fmaf(xb[o.z + c], w.z, v);
        v = fmaf(xb[o.w + c], w.w, v);
        m = fmaxf(m, v);
        if ((j & 3) == 3) {
            buf[c * 8 + (j >> 2)] = m;
            m = -3.402823466e38f;
        }
    }
    __syncthreads();
    const size_t row = (size_t)b * Lv + l;
    const float* bp = buf + c * 8;
    __half h[8], lo[8];
#pragma unroll
    for (int j = 0; j < 8; j++) split_h(bp[j], h[j], lo[j]);
    *(uint4*)&g_flath[row * DFC + c * 8] = *(uint4*)h;
    *(uint4*)&g_flatl[row * DFC + c * 8] = *(uint4*)lo;
}

// ---------------- persistent fused dual-GEMM (fp16x3), 4 warps of 64x64
// R14: R12 structure; only the per-mi MMA issue order is pass-major over ni.
#define LDH 40
#define HT (128 * LDH)
#define GH_SMEM (8 * HT * 2)

__global__ __launch_bounds__(128, 2) void gemm_fused_kernel(const float* __restrict__ b1,
                                                            const float* __restrict__ b2) {
    extern __shared__ __half hmem[];
    const uint32_t sb = smem_u32(hmem);
    const int tid = threadIdx.x;
    const int wid = tid >> 5, lane = tid & 31;
    const int wm = wid & 1, wn = wid >> 1;
    const int lrow = tid >> 2, lchunk = tid & 3;

    for (int t = blockIdx.x; t < 2 * NT; t += gridDim.x) {
        const int isg1 = (t < NT);
        const int u = isg1 ? t : t - NT;
        const int row = u >> 3, col = u & 7;
        const __half *Ah, *Al, *Wh, *Wl;
        const float* bias;
        if (isg1) {
            Ah = g_flath; Al = g_flatl; Wh = g_w1h; Wl = g_w1l; bias = b1;
        } else {
            if (tid == 0) {
                volatile int* rd = &g_rowdone[row];
                while (*rd < 8) __nanosleep(64);
            }
            __syncthreads();
            __threadfence();
            Ah = g_h1h; Al = g_h1l; Wh = g_w2h; Wl = g_w2l; bias = b2;
        }
        const int rowbase = row * 128;
        const int colbase = col * 128;

        wmma::fragment<wmma::accumulator, 16, 16, 16, float> acc[4][4];
#pragma unroll
        for (int mi = 0; mi < 4; mi++)
#pragma unroll
            for (int ni = 0; ni < 4; ni++) wmma::fill_fragment(acc[mi][ni], 0.f);

        auto load_stage = [&](int s, int k0) {
#pragma unroll
            for (int r = 0; r < 4; r++) {
                const int rr = lrow + r * 32;
                const uint32_t so = (uint32_t)((s * 4 * HT + rr * LDH + lchunk * 8) * 2);
                const size_t ga = (size_t)(rowbase + rr) * DFC + k0 + lchunk * 8;
                const size_t gb = (size_t)(colbase + rr) * DFC + k0 + lchunk * 8;
                cp_async16(sb + so,              &Ah[ga]);
                cp_async16(sb + so + HT * 2,     &Al[ga]);
                cp_async16(sb + so + 2 * HT * 2, &Wh[gb]);
                cp_async16(sb + so + 3 * HT * 2, &Wl[gb]);
            }
        };

        load_stage(0, 0);
        CP_COMMIT();

        const int nk = DFC / 32;
        for (int i = 0; i < nk; i++) {
            const int s = i & 1;
            if (i + 1 < nk) {
                load_stage(s ^ 1, (i + 1) * 32);
                CP_COMMIT();
                CP_WAIT1();
            } else {
                CP_WAIT0();
            }
            __syncthreads();

            const __half* sAh = hmem + s * 4 * HT;
            const __half* sAl = sAh + HT;
            const __half* sBh = sAh + 2 * HT;
            const __half* sBl = sAh + 3 * HT;
#pragma unroll
            for (int kk = 0; kk < 32; kk += 16) {
                wmma::fragment<wmma::matrix_b, 16, 16, 16, __half, wmma::col_major> fbh[4], fbl[4];
#pragma unroll
                for (int ni = 0; ni < 4; ni++) {
                    const int n0 = wn * 64 + ni * 16;
                    wmma::load_matrix_sync(fbh[ni], sBh + n0 * LDH + kk, LDH);
                    wmma::load_matrix_sync(fbl[ni], sBl + n0 * LDH + kk, LDH);
                }
#pragma unroll
                for (int mi = 0; mi < 4; mi++) {
                    const int m0 = wm * 64 + mi * 16;
                    wmma::fragment<wmma::matrix_a, 16, 16, 16, __half, wmma::row_major> fah, fal;
                    wmma::load_matrix_sync(fah, sAh + m0 * LDH + kk, LDH);
                    wmma::load_matrix_sync(fal, sAl + m0 * LDH + kk, LDH);
                    // pass-major over ni: dependent MMAs on acc[mi][ni] are 4 apart
#pragma unroll
                    for (int ni = 0; ni < 4; ni++)
                        wmma::mma_sync(acc[mi][ni], fah, fbh[ni], acc[mi][ni]);
#pragma unroll
                    for (int ni = 0; ni < 4; ni++)
                        wmma::mma_sync(acc[mi][ni], fal, fbh[ni], acc[mi][ni]);
#pragma unroll
                    for (int ni = 0; ni < 4; ni++)
                        wmma::mma_sync(acc[mi][ni], fah, fbl[ni], acc[mi][ni]);
                }
            }
            __syncthreads();
        }

        float* stg = (float*)hmem + wid * (16 * STG_LD);
        const int er = lane >> 1;
        const int ec = (lane & 1) * 8;
#pragma unroll
        for (int mi = 0; mi < 4; mi++)
#pragma unroll
            for (int ni = 0; ni < 4; ni++) {
                wmma::store_matrix_sync(stg, acc[mi][ni], STG_LD, wmma::mem_row_major);
                __syncwarp();
                const int gr = rowbase + wm * 64 + mi * 16 + er;
                const int gc = colbase + wn * 64 + ni * 16 + ec;
                const float* sp = stg + er * STG_LD + ec;
                const float* bp = bias + gc;
                float r[8];
#pragma unroll
                for (int j = 0; j < 8; j++) r[j] = fmaxf(sp[j] + bp[j], 0.f);
                if (isg1) {
                    __half h[8], lo[8];
#pragma unroll
                    for (int j = 0; j < 8; j++) split_h(r[j], h[j], lo[j]);
                    *(uint4*)&g_h1h[(size_t)gr * DFC + gc] = *(uint4*)h;
                    *(uint4*)&g_h1l[(size_t)gr * DFC + gc] = *(uint4*)lo;
                } else {
                    *(float4*)&g_h2[(size_t)gr * DFC + gc] = make_float4(r[0], r[1], r[2], r[3]);
                    *(float4*)&g_h2[(size_t)gr * DFC + gc + 4] = make_float4(r[4], r[5], r[6], r[7]);
                }
                __syncwarp();
            }

        __threadfence();
        __syncthreads();
        if (isg1 && tid == 0) atomicAdd(&g_rowdone[row], 1);
    }
}

// ---------------- K5: logits -> softmax -> mask/key (warp per line)
__global__ __launch_bounds__(256) void head_kernel(const float* __restrict__ w3,
                                                   const float* __restrict__ b3) {
    const int line = blockIdx.x * 8 + (threadIdx.x >> 5);
    if (line >= NLINES) return;
    const int lane = threadIdx.x & 31;
    const float4* hr = (const float4*)(g_h2 + (size_t)line * DFC);
    const float4* wr0 = (const float4*)(w3);
    const float4* wr1 = (const float4*)(w3 + DFC);
    const float4* wr2 = (const float4*)(w3 + 2 * DFC);
    const float4* wr3 = (const float4*)(w3 + 3 * DFC);
    float a0 = 0.f, a1 = 0.f, a2 = 0.f, a3 = 0.f;
    for (int k = lane; k < 256; k += 32) {
        float4 h = hr[k];
        float4 x;
        x = wr0[k]; a0 += h.x * x.x + h.y * x.y + h.z * x.z + h.w * x.w;
        x = wr1[k]; a1 += h.x * x.x + h.y * x.y + h.z * x.z + h.w * x.w;
        x = wr2[k]; a2 += h.x * x.x + h.y * x.y + h.z * x.z + h.w * x.w;
        x = wr3[k]; a3 += h.x * x.x + h.y * x.y + h.z * x.z + h.w * x.w;
    }
#pragma unroll
    for (int d = 16; d > 0; d >>= 1) {
        a0 += __shfl_xor_sync(0xffffffffu, a0, d);
        a1 += __shfl_xor_sync(0xffffffffu, a1, d);
        a2 += __shfl_xor_sync(0xffffffffu, a2, d);
        a3 += __shfl_xor_sync(0xffffffffu, a3, d);
    }
    if (lane == 0) {
        float l0 = a0 + b3[0], l1 = a1 + b3[1], l2 = a2 + b3[2], l3 = a3 + b3[3];
        float mx = fmaxf(fmaxf(l0, l1), fmaxf(l2, l3));
        float e0 = expf(l0 - mx), e1 = expf(l1 - mx), e2 = expf(l2 - mx), e3 = expf(l3 - mx);
        float inv = 1.f / (e0 + e1 + e2 + e3);
        float s0 = e0 * inv, s1 = e1 * inv, s2 = e2 * inv, s3 = e3 * inv;
        int am = 0; float bm = l0;
        if (l1 > bm) { am = 1; bm = l1; }
        if (l2 > bm) { am = 2; bm = l2; }
        if (l3 > bm) { am = 3; bm = l3; }
        bool mask = (s1 > 0.25f || s2 > 0.25f || s3 > 0.25f) && (s0 < 0.25f);
        *(float4*)&g_s[line * 4] = make_float4(s0, s1, s2, s3);
        g_key[line] = mask ? am : -1;
    }
}

// ---------------- K6: per-batch stable counting sort + cyclic gather to output
__global__ __launch_bounds__(1024) void select_kernel(const float* __restrict__ lines,
                                                      float* __restrict__ out) {
    const int b = blockIdx.x;
    const int tid = threadIdx.x;
    const int lane = tid & 31, wid = tid >> 5;
    __shared__ int warp_sums[32];
    __shared__ int s_base;
    if (tid == 0) s_base = 0;
    const int* keyb = g_key + b * Lv;
    int* ordb = g_order + b * Lv;

    for (int kv = 3; kv >= 0; kv--) {
        for (int chunk = 0; chunk < Lv; chunk += 1024) {
            __syncthreads();
            int i = chunk + tid;
            int pred = (i < Lv && keyb[i] == kv) ? 1 : 0;
            int incl = pred;
#pragma unroll
            for (int d = 1; d < 32; d <<= 1) {
                int v = __shfl_up_sync(0xffffffffu, incl, d);
                if (lane >= d) incl += v;
            }
            if (lane == 31) warp_sums[wid] = incl;
            __syncthreads();
            if (wid == 0) {
                int inc2 = warp_sums[lane];
#pragma unroll
                for (int d = 1; d < 32; d <<= 1) {
                    int t = __shfl_up_sync(0xffffffffu, inc2, d);
                    if (lane >= d) inc2 += t;
                }
                warp_sums[lane] = inc2;
            }
            __syncthreads();
            int excl = incl - pred + (wid > 0 ? warp_sums[wid - 1] : 0);
            int total = warp_sums[31];
            int base = s_base;
            if (pred) ordb[base + excl] = i;
            __syncthreads();
            if (tid == 0) s_base = base + total;
        }
    }
    __syncthreads();
    const int cnt = s_base;

    float* out_lines = out + (size_t)b * NOUT * 4;
    float* out_scores = out + (size_t)Bv * NOUT * 4 + (size_t)b * NOUT * 4;
    for (int i = tid; i < NOUT; i += 1024) {
        float4 lv = make_float4(0.f, 0.f, 0.f, 0.f);
        float4 sv = make_float4(0.f, 0.f, 0.f, 0.f);
        if (cnt > 0) {
            int sel = ordb[i % cnt];
            lv = *(const float4*)&lines[((size_t)b * Lv + sel) * 4];
            sv = *(const float4*)&g_s[(b * Lv + sel) * 4];
        }
        *(float4*)&out_lines[(size_t)i * 4] = lv;
        *(float4*)&out_scores[(size_t)i * 4] = sv;
    }
}

// ---------------- launch ----------------
extern "C" void kernel_launch(void* const* d_in, const int* in_sizes, int n_in,
                              void* d_out, int out_size) {
    const float* feature = (const float*)d_in[0];
    const float* lines   = (const float*)d_in[1];
    const float* fc1_w   = (const float*)d_in[2];
    const float* fc1_b   = (const float*)d_in[3];
    const float* w1      = (const float*)d_in[4];
    const float* b1      = (const float*)d_in[5];
    const float* w2      = (const float*)d_in[6];
    const float* b2      = (const float*)d_in[7];
    const float* w3      = (const float*)d_in[8];
    const float* b3      = (const float*)d_in[9];
    float* out = (float*)d_out;

    cudaFuncSetAttribute(gemm_fused_kernel, cudaFuncAttributeMaxDynamicSharedMemorySize, GH_SMEM);
    cudaFuncSetAttribute(conv_wmma_kernel, cudaFuncAttributeMaxDynamicSharedMemorySize, CC_SMEM);

    int dev = 0;
    cudaGetDevice(&dev);
    int nsm = 0;
    cudaDeviceGetAttribute(&nsm, cudaDevAttrMultiProcessorCount, dev);
    int nblk = 0;
    cudaOccupancyMaxActiveBlocksPerMultiprocessor(&nblk, gemm_fused_kernel, 128, GH_SMEM);
    if (nblk < 1) nblk = 1;
    int grid = nsm * nblk;
    if (grid > 2 * NT) grid = 2 * NT;

    split_w_kernel<<<(2 * W1F4 + CWF4 + 255) / 256, 256>>>(w1, w2, fc1_w);
    conv_wmma_kernel<<<dim3(HW / 128, Bv), 256, CC_SMEM>>>(feature, fc1_b);
    sample_pool_kernel<<<dim3(Lv, Bv), 128>>>(lines);
    gemm_fused_kernel<<<grid, 128, GH_SMEM>>>(b1, b2);
    head_kernel<<<(NLINES + 7) / 8, 256>>>(w3, b3);
    select_kernel<<<Bv, 1024>>>(lines, out);
}

// round 15
// speedup vs baseline: 1.0675x; 1.0524x over previous
#include <cuda_runtime.h>
#include <cuda_fp16.h>
#include <cstdint>
#include <mma.h>

using namespace nvcuda;

#define Bv 4
#define CIN 256
#define HW 65536
#define Lv 5000
#define DLOI 128
#define DFC 1024
#define NOUT 2500
#define NLINES (Bv*Lv)
#define NPAD 20096            // 157 * 128 row tiles
#define NROWT (NPAD / 128)    // 157
#define NT (NROWT * (DFC / 128))   // 1256 tiles per gemm

// ---------------- scratch (static __device__, no allocs) ----------------
__device__ float  g_x[(size_t)Bv * HW * DLOI];
__device__ __half g_flath[(size_t)NPAD * DFC];
__device__ __half g_flatl[(size_t)NPAD * DFC];
__device__ __half g_h1h[(size_t)NPAD * DFC];
__device__ __half g_h1l[(size_t)NPAD * DFC];
__device__ __half g_w1h[DFC * DFC];
__device__ __half g_w1l[DFC * DFC];
__device__ __half g_w2h[DFC * DFC];
__device__ __half g_w2l[DFC * DFC];
__device__ __half g_cwh[DLOI * CIN];
__device__ __half g_cwl[DLOI * CIN];
__device__ int    g_rowdone[NROWT];
__device__ float  g_plog[(size_t)NPAD * 16 * 4];    // partial logits per 64-col chunk
__device__ float  g_s[NLINES * 4];
__device__ int    g_key[NLINES];
__device__ int    g_order[NLINES];

__device__ __forceinline__ uint32_t smem_u32(const void* p) {
    uint32_t a;
    asm("{ .reg .u64 t; cvta.to.shared.u64 t, %1; cvt.u32.u64 %0, t; }" : "=r"(a) : "l"(p));
    return a;
}
__device__ __forceinline__ void cp_async16(uint32_t dst, const void* src) {
    asm volatile("cp.async.cg.shared.global [%0], [%1], 16;" :: "r"(dst), "l"(src));
}
#define CP_COMMIT() asm volatile("cp.async.commit_group;" ::: "memory")
#define CP_WAIT1()  asm volatile("cp.async.wait_group 1;" ::: "memory")
#define CP_WAIT0()  asm volatile("cp.async.wait_group 0;" ::: "memory")

__device__ __forceinline__ void split_h(float v, __half& h, __half& l) {
    h = __float2half_rn(v);
    l = __float2half_rn(v - __half2float(h));
}
__device__ __forceinline__ void split4_to(const float4 v, __half* h, __half* l) {
    split_h(v.x, h[0], l[0]); split_h(v.y, h[1], l[1]);
    split_h(v.z, h[2], l[2]); split_h(v.w, h[3], l[3]);
}

// ---------------- K0: split w1/w2/fc1_w into hi/lo; block 0 zeros g_rowdone
#define W1F4 (DFC * DFC / 4)
#define CWF4 (DLOI * CIN / 4)
__global__ __launch_bounds__(256) void split_w_kernel(const float* __restrict__ w1,
                                                      const float* __restrict__ w2,
                                                      const float* __restrict__ cw) {
    if (blockIdx.x == 0 && threadIdx.x < NROWT) g_rowdone[threadIdx.x] = 0;
    const int i4 = blockIdx.x * blockDim.x + threadIdx.x;
    __half h[4], l[4];
    if (i4 < W1F4) {
        split4_to(*(const float4*)&w1[(size_t)i4 * 4], h, l);
        *(uint2*)&g_w1h[(size_t)i4 * 4] = *(uint2*)h;
        *(uint2*)&g_w1l[(size_t)i4 * 4] = *(uint2*)l;
    } else if (i4 < 2 * W1F4) {
        int j = i4 - W1F4;
        split4_to(*(const float4*)&w2[(size_t)j * 4], h, l);
        *(uint2*)&g_w2h[(size_t)j * 4] = *(uint2*)h;
        *(uint2*)&g_w2l[(size_t)j * 4] = *(uint2*)l;
    } else if (i4 < 2 * W1F4 + CWF4) {
        int j = i4 - 2 * W1F4;
        split4_to(*(const float4*)&cw[(size_t)j * 4], h, l);
        *(uint2*)&g_cwh[(size_t)j * 4] = *(uint2*)h;
        *(uint2*)&g_cwl[(size_t)j * 4] = *(uint2*)l;
    }
}

// ---------------- K1: conv1x1 fp16x3 wmma (R12 form), fused f32->hi/lo split loader
#define CLA 136
#define CLB 40
#define CAT (32 * CLA)
#define CBT (128 * CLB)
#define CSTG (2 * (CAT + CBT))
#define CC_SMEM (2 * CSTG * 2)
#define STG_LD 20

__global__ __launch_bounds__(256, 2) void conv_wmma_kernel(const float* __restrict__ feat,
                                                           const float* __restrict__ bias) {
    extern __shared__ __half cmem[];
    const uint32_t sb = smem_u32(cmem);
    const int tid = threadIdx.x;
    const int wid = tid >> 5, lane = tid & 31;
    const int wm = wid & 3, wn = wid >> 2;
    const int b = blockIdx.y;
    const int p0 = blockIdx.x * 128;

    wmma::fragment<wmma::accumulator, 16, 16, 16, float> acc[2][4];
#pragma unroll
    for (int mi = 0; mi < 2; mi++)
#pragma unroll
        for (int ni = 0; ni < 4; ni++) wmma::fill_fragment(acc[mi][ni], 0.f);

    float4 cur[4];
    auto ldgA = [&](int c0) {
#pragma unroll
        for (int r = 0; r < 4; r++) {
            int slot = tid + r * 256;
            int k = slot >> 5, c4 = slot & 31;
            cur[r] = *(const float4*)&feat[((size_t)b * CIN + c0 + k) * HW + p0 + c4 * 4];
        }
    };
    auto stsA = [&](int s) {
#pragma unroll
        for (int r = 0; r < 4; r++) {
            int slot = tid + r * 256;
            int k = slot >> 5, c4 = slot & 31;
            __half h[4], l[4];
            split4_to(cur[r], h, l);
            __half* base = cmem + s * CSTG + k * CLA + c4 * 4;
            *(uint2*)base = *(uint2*)h;
            *(uint2*)(base + CAT) = *(uint2*)l;
        }
    };
    auto cpB = [&](int s, int c0) {
#pragma unroll
        for (int r = 0; r < 2; r++) {
            int slot = tid + r * 256;
            int n = slot >> 2, ch = slot & 3;
            size_t gw = (size_t)n * CIN + c0 + ch * 8;
            uint32_t so = (uint32_t)((s * CSTG + 2 * CAT + n * CLB + ch * 8) * 2);
            cp_async16(sb + so, &g_cwh[gw]);
            cp_async16(sb + so + CBT * 2, &g_cwl[gw]);
        }
    };

    ldgA(0);
    cpB(0, 0);
    CP_COMMIT();

    const int nk = CIN / 32;
    for (int i = 0; i < nk; i++) {
        const int s = i & 1;
        stsA(s);
        if (i + 1 < nk) ldgA((i + 1) * 32);
        CP_WAIT0();
        __syncthreads();
        if (i + 1 < nk) { cpB(s ^ 1, (i + 1) * 32); CP_COMMIT(); }

        const __half* sAh = cmem + s * CSTG;
        const __half* sAl = sAh + CAT;
        const __half* sBh = sAh + 2 * CAT;
        const __half* sBl = sBh + CBT;
#pragma unroll
        for (int kk = 0; kk < 32; kk += 16) {
            wmma::fragment<wmma::matrix_a, 16, 16, 16, __half, wmma::col_major> fah[2], fal[2];
#pragma unroll
            for (int mi = 0; mi < 2; mi++) {
                const int m0 = wm * 32 + mi * 16;
                wmma::load_matrix_sync(fah[mi], sAh + kk * CLA + m0, CLA);
                wmma::load_matrix_sync(fal[mi], sAl + kk * CLA + m0, CLA);
            }
#pragma unroll
            for (int ni = 0; ni < 4; ni++) {
                const int n0 = wn * 64 + ni * 16;
                wmma::fragment<wmma::matrix_b, 16, 16, 16, __half, wmma::col_major> fbh, fbl;
                wmma::load_matrix_sync(fbh, sBh + n0 * CLB + kk, CLB);
                wmma::load_matrix_sync(fbl, sBl + n0 * CLB + kk, CLB);
#pragma unroll
                for (int mi = 0; mi < 2; mi++) {
                    wmma::mma_sync(acc[mi][ni], fah[mi], fbh, acc[mi][ni]);
                    wmma::mma_sync(acc[mi][ni], fah[mi], fbl, acc[mi][ni]);
                    wmma::mma_sync(acc[mi][ni], fal[mi], fbh, acc[mi][ni]);
                }
            }
        }
        __syncthreads();
    }

    float* stg = (float*)cmem + wid * (16 * STG_LD);
    const int er = lane >> 1;
    const int ec = (lane & 1) * 8;
    float* xb = g_x + (size_t)b * HW * DLOI;
#pragma unroll
    for (int mi = 0; mi < 2; mi++)
#pragma unroll
        for (int ni = 0; ni < 4; ni++) {
            wmma::store_matrix_sync(stg, acc[mi][ni], STG_LD, wmma::mem_row_major);
            __syncwarp();
            const int gp = p0 + wm * 32 + mi * 16 + er;
            const int go = wn * 64 + ni * 16 + ec;
            const float* sp = stg + er * STG_LD + ec;
            const float* bp = bias + go;
            *(float4*)&xb[(size_t)gp * DLOI + go] =
                make_float4(sp[0] + bp[0], sp[1] + bp[1], sp[2] + bp[2], sp[3] + bp[3]);
            *(float4*)&xb[(size_t)gp * DLOI + go + 4] =
                make_float4(sp[4] + bp[4], sp[5] + bp[5], sp[6] + bp[6], sp[7] + bp[7]);
            __syncwarp();
        }
}

// ---------------- K2: cooperative sampler
__global__ __launch_bounds__(128) void sample_pool_kernel(const float* __restrict__ lines) {
    const int b = blockIdx.y, l = blockIdx.x, c = threadIdx.x;
    __shared__ int4   s_o[32];
    __shared__ float4 s_wt[32];
    __shared__ float  buf[DFC];

    if (c < 32) {
        const float* ln = lines + ((size_t)b * Lv + l) * 4;
        float lam = (1.0f / 31.0f) * (float)c;
        float px = ln[0] * lam + ln[2] * (1.f - lam) - 0.5f;
        float py = ln[1] * lam + ln[3] * (1.f - lam) - 0.5f;
        float px0 = fminf(fmaxf(floorf(px), 0.f), 255.f);
        float py0 = fminf(fmaxf(floorf(py), 0.f), 255.f);
        float px1 = fminf(px0 + 1.f, 255.f);
        float py1 = fminf(py0 + 1.f, 255.f);
        int ix0 = (int)px0, iy0 = (int)py0, ix1 = (int)px1, iy1 = (int)py1;
        s_o[c] = make_int4((ix0 * 256 + iy0) * DLOI, (ix1 * 256 + iy0) * DLOI,
                           (ix0 * 256 + iy1) * DLOI, (ix1 * 256 + iy1) * DLOI);
        s_wt[c] = make_float4((px1 - px) * (py1 - py), (px - px0) * (py1 - py),
                              (px1 - px) * (py - py0), (px - px0) * (py - py0));
    }
    __syncthreads();

    const float* xb = g_x + (size_t)b * HW * DLOI;
    float m = -3.402823466e38f;
#pragma unroll
    for (int j = 0; j < 32; j++) {
        int4 o = s_o[j];
        float4 w = s_wt[j];
        float v = xb[o.x + c] * w.x;
        v = fmaf(xb[o.y + c], w.y, v);
        v = fmaf(xb[o.z + c], w.z, v);
        v = fmaf(xb[o.w + c], w.w, v);
        m = fmaxf(m, v);
        if ((j & 3) == 3) {
            buf[c * 8 + (j >> 2)] = m;
            m = -3.402823466e38f;
        }
    }
    __syncthreads();
    const size_t row = (size_t)b * Lv + l;
    const float* bp = buf + c * 8;
    __half h[8], lo[8];
#pragma unroll
    for (int j = 0; j < 8; j++) split_h(bp[j], h[j], lo[j]);
    *(uint4*)&g_flath[row * DFC + c * 8] = *(uint4*)h;
    *(uint4*)&g_flatl[row * DFC + c * 8] = *(uint4*)lo;
}

// ---------------- persistent fused dual-GEMM (fp16x3), 4 warps of 64x64
// Mainloop = R12 exact. gemm2 epilogue fuses the w3 head GEMV into partial
// logits (plain stores, deterministic), eliminating h2 + head kernel.
#define LDH 40
#define HT (128 * LDH)
#define GH_SMEM (8 * HT * 2 + 16384)     // +16KB persistent w3 smem copy

__global__ __launch_bounds__(128, 2) void gemm_fused_kernel(const float* __restrict__ b1,
                                                            const float* __restrict__ b2,
                                                            const float* __restrict__ w3) {
    extern __shared__ __half hmem[];
    const uint32_t sb = smem_u32(hmem);
    const int tid = threadIdx.x;
    const int wid = tid >> 5, lane = tid & 31;
    const int wm = wid & 1, wn = wid >> 1;
    const int lrow = tid >> 2, lchunk = tid & 3;

    // persistent w3 copy at the end of smem (beyond the 81920B stage region)
    float* w3s = (float*)hmem + 20480;
    for (int i = tid; i < 4 * DFC; i += 128) w3s[i] = w3[i];

    for (int t = blockIdx.x; t < 2 * NT; t += gridDim.x) {
        const int isg1 = (t < NT);
        const int u = isg1 ? t : t - NT;
        const int row = u >> 3, col = u & 7;
        const __half *Ah, *Al, *Wh, *Wl;
        const float* bias;
        if (isg1) {
            Ah = g_flath; Al = g_flatl; Wh = g_w1h; Wl = g_w1l; bias = b1;
        } else {
            if (tid == 0) {
                volatile int* rd = &g_rowdone[row];
                while (*rd < 8) __nanosleep(64);
            }
            __syncthreads();
            __threadfence();
            Ah = g_h1h; Al = g_h1l; Wh = g_w2h; Wl = g_w2l; bias = b2;
        }
        const int rowbase = row * 128;
        const int colbase = col * 128;

        wmma::fragment<wmma::accumulator, 16, 16, 16, float> acc[4][4];
#pragma unroll
        for (int mi = 0; mi < 4; mi++)
#pragma unroll
            for (int ni = 0; ni < 4; ni++) wmma::fill_fragment(acc[mi][ni], 0.f);

        auto load_stage = [&](int s, int k0) {
#pragma unroll
            for (int r = 0; r < 4; r++) {
                const int rr = lrow + r * 32;
                const uint32_t so = (uint32_t)((s * 4 * HT + rr * LDH + lchunk * 8) * 2);
                const size_t ga = (size_t)(rowbase + rr) * DFC + k0 + lchunk * 8;
                const size_t gb = (size_t)(colbase + rr) * DFC + k0 + lchunk * 8;
                cp_async16(sb + so,              &Ah[ga]);
                cp_async16(sb + so + HT * 2,     &Al[ga]);
                cp_async16(sb + so + 2 * HT * 2, &Wh[gb]);
                cp_async16(sb + so + 3 * HT * 2, &Wl[gb]);
            }
        };

        load_stage(0, 0);
        CP_COMMIT();

        const int nk = DFC / 32;
        for (int i = 0; i < nk; i++) {
            const int s = i & 1;
            if (i + 1 < nk) {
                load_stage(s ^ 1, (i + 1) * 32);
                CP_COMMIT();
                CP_WAIT1();
            } else {
                CP_WAIT0();
            }
            __syncthreads();

            const __half* sAh = hmem + s * 4 * HT;
            const __half* sAl = sAh + HT;
            const __half* sBh = sAh + 2 * HT;
            const __half* sBl = sAh + 3 * HT;
#pragma unroll
            for (int kk = 0; kk < 32; kk += 16) {
                // R12 exact ordering (best measured): B frags preloaded,
                // A frags per-mi, 3 MMAs grouped per (mi,ni).
                wmma::fragment<wmma::matrix_b, 16, 16, 16, __half, wmma::col_major> fbh[4], fbl[4];
#pragma unroll
                for (int ni = 0; ni < 4; ni++) {
                    const int n0 = wn * 64 + ni * 16;
                    wmma::load_matrix_sync(fbh[ni], sBh + n0 * LDH + kk, LDH);
                    wmma::load_matrix_sync(fbl[ni], sBl + n0 * LDH + kk, LDH);
                }
#pragma unroll
                for (int mi = 0; mi < 4; mi++) {
                    const int m0 = wm * 64 + mi * 16;
                    wmma::fragment<wmma::matrix_a, 16, 16, 16, __half, wmma::row_major> fah, fal;
                    wmma::load_matrix_sync(fah, sAh + m0 * LDH + kk, LDH);
                    wmma::load_matrix_sync(fal, sAl + m0 * LDH + kk, LDH);
#pragma unroll
                    for (int ni = 0; ni < 4; ni++) {
                        wmma::mma_sync(acc[mi][ni], fah, fbh[ni], acc[mi][ni]);
                        wmma::mma_sync(acc[mi][ni], fah, fbl[ni], acc[mi][ni]);
                        wmma::mma_sync(acc[mi][ni], fal, fbh[ni], acc[mi][ni]);
                    }
                }
            }
            __syncthreads();
        }

        float* stg = (float*)hmem + wid * (16 * STG_LD);
        const int er = lane >> 1;
        const int ec = (lane & 1) * 8;
#pragma unroll
        for (int mi = 0; mi < 4; mi++) {
            const int gr = rowbase + wm * 64 + mi * 16 + er;
            float p0 = 0.f, p1 = 0.f, p2 = 0.f, p3 = 0.f;   // partial logits (gemm2)
#pragma unroll
            for (int ni = 0; ni < 4; ni++) {
                wmma::store_matrix_sync(stg, acc[mi][ni], STG_LD, wmma::mem_row_major);
                __syncwarp();
                const int gc = colbase + wn * 64 + ni * 16 + ec;
                const float* sp = stg + er * STG_LD + ec;
                const float* bp = bias + gc;
                float r[8];
#pragma unroll
                for (int j = 0; j < 8; j++) r[j] = fmaxf(sp[j] + bp[j], 0.f);
                if (isg1) {
                    __half h[8], lo[8];
#pragma unroll
                    for (int j = 0; j < 8; j++) split_h(r[j], h[j], lo[j]);
                    *(uint4*)&g_h1h[(size_t)gr * DFC + gc] = *(uint4*)h;
                    *(uint4*)&g_h1l[(size_t)gr * DFC + gc] = *(uint4*)lo;
                } else {
                    const float* wp0 = w3s + gc;
                    const float* wp1 = w3s + DFC + gc;
                    const float* wp2 = w3s + 2 * DFC + gc;
                    const float* wp3 = w3s + 3 * DFC + gc;
#pragma unroll
                    for (int j = 0; j < 8; j++) {
                        p0 = fmaf(r[j], wp0[j], p0);
                        p1 = fmaf(r[j], wp1[j], p1);
                        p2 = fmaf(r[j], wp2[j], p2);
                        p3 = fmaf(r[j], wp3[j], p3);
                    }
                }
                __syncwarp();
            }
            if (!isg1) {
                // combine the two lanes of each row (ec=0 / ec=8)
                p0 += __shfl_xor_sync(0xffffffffu, p0, 1);
                p1 += __shfl_xor_sync(0xffffffffu, p1, 1);
                p2 += __shfl_xor_sync(0xffffffffu, p2, 1);
                p3 += __shfl_xor_sync(0xffffffffu, p3, 1);
                if ((lane & 1) == 0) {
                    *(float4*)&g_plog[(((size_t)gr * 16) + col * 2 + wn) * 4] =
                        make_float4(p0, p1, p2, p3);
                }
            }
        }

        __threadfence();
        __syncthreads();
        if (isg1 && tid == 0) atomicAdd(&g_rowdone[row], 1);
    }
}

// ---------------- K5: head2 — sum 16 partial logits (fixed order), softmax, mask/key
__global__ __launch_bounds__(256) void head2_kernel(const float* __restrict__ b3) {
    const int line = blockIdx.x * 256 + threadIdx.x;
    if (line >= NLINES) return;
    float l0 = b3[0], l1 = b3[1], l2 = b3[2], l3 = b3[3];
    const float4* pp = (const float4*)&g_plog[(size_t)line * 16 * 4];
#pragma unroll
    for (int k = 0; k < 16; k++) {
        float4 p = pp[k];
        l0 += p.x; l1 += p.y; l2 += p.z; l3 += p.w;
    }
    float mx = fmaxf(fmaxf(l0, l1), fmaxf(l2, l3));
    float e0 = expf(l0 - mx), e1 = expf(l1 - mx), e2 = expf(l2 - mx), e3 = expf(l3 - mx);
    float inv = 1.f / (e0 + e1 + e2 + e3);
    float s0 = e0 * inv, s1 = e1 * inv, s2 = e2 * inv, s3 = e3 * inv;
    int am = 0; float bm = l0;
    if (l1 > bm) { am = 1; bm = l1; }
    if (l2 > bm) { am = 2; bm = l2; }
    if (l3 > bm) { am = 3; bm = l3; }
    bool mask = (s1 > 0.25f || s2 > 0.25f || s3 > 0.25f) && (s0 < 0.25f);
    *(float4*)&g_s[line * 4] = make_float4(s0, s1, s2, s3);
    g_key[line] = mask ? am : -1;
}

// ---------------- K6: per-batch stable counting sort + cyclic gather to output
__global__ __launch_bounds__(1024) void select_kernel(const float* __restrict__ lines,
                                                      float* __restrict__ out) {
    const int b = blockIdx.x;
    const int tid = threadIdx.x;
    const int lane = tid & 31, wid = tid >> 5;
    __shared__ int warp_sums[32];
    __shared__ int s_base;
    if (tid == 0) s_base = 0;
    const int* keyb = g_key + b * Lv;
    int* ordb = g_order + b * Lv;

    for (int kv = 3; kv >= 0; kv--) {
        for (int chunk = 0; chunk < Lv; chunk += 1024) {
            __syncthreads();
            int i = chunk + tid;
            int pred = (i < Lv && keyb[i] == kv) ? 1 : 0;
            int incl = pred;
#pragma unroll
            for (int d = 1; d < 32; d <<= 1) {
                int v = __shfl_up_sync(0xffffffffu, incl, d);
                if (lane >= d) incl += v;
            }
            if (lane == 31) warp_sums[wid] = incl;
            __syncthreads();
            if (wid == 0) {
                int inc2 = warp_sums[lane];
#pragma unroll
                for (int d = 1; d < 32; d <<= 1) {
                    int t = __shfl_up_sync(0xffffffffu, inc2, d);
                    if (lane >= d) inc2 += t;
                }
                warp_sums[lane] = inc2;
            }
            __syncthreads();
            int excl = incl - pred + (wid > 0 ? warp_sums[wid - 1] : 0);
            int total = warp_sums[31];
            int base = s_base;
            if (pred) ordb[base + excl] = i;
            __syncthreads();
            if (tid == 0) s_base = base + total;
        }
    }
    __syncthreads();
    const int cnt = s_base;

    float* out_lines = out + (size_t)b * NOUT * 4;
    float* out_scores = out + (size_t)Bv * NOUT * 4 + (size_t)b * NOUT * 4;
    for (int i = tid; i < NOUT; i += 1024) {
        float4 lv = make_float4(0.f, 0.f, 0.f, 0.f);
        float4 sv = make_float4(0.f, 0.f, 0.f, 0.f);
        if (cnt > 0) {
            int sel = ordb[i % cnt];
            lv = *(const float4*)&lines[((size_t)b * Lv + sel) * 4];
            sv = *(const float4*)&g_s[(b * Lv + sel) * 4];
        }
        *(float4*)&out_lines[(size_t)i * 4] = lv;
        *(float4*)&out_scores[(size_t)i * 4] = sv;
    }
}

// ---------------- launch ----------------
extern "C" void kernel_launch(void* const* d_in, const int* in_sizes, int n_in,
                              void* d_out, int out_size) {
    const float* feature = (const float*)d_in[0];
    const float* lines   = (const float*)d_in[1];
    const float* fc1_w   = (const float*)d_in[2];
    const float* fc1_b   = (const float*)d_in[3];
    const float* w1      = (const float*)d_in[4];
    const float* b1      = (const float*)d_in[5];
    const float* w2      = (const float*)d_in[6];
    const float* b2      = (const float*)d_in[7];
    const float* w3      = (const float*)d_in[8];
    const float* b3      = (const float*)d_in[9];
    float* out = (float*)d_out;

    cudaFuncSetAttribute(gemm_fused_kernel, cudaFuncAttributeMaxDynamicSharedMemorySize, GH_SMEM);
    cudaFuncSetAttribute(conv_wmma_kernel, cudaFuncAttributeMaxDynamicSharedMemorySize, CC_SMEM);

    int dev = 0;
    cudaGetDevice(&dev);
    int nsm = 0;
    cudaDeviceGetAttribute(&nsm, cudaDevAttrMultiProcessorCount, dev);
    int nblk = 0;
    cudaOccupancyMaxActiveBlocksPerMultiprocessor(&nblk, gemm_fused_kernel, 128, GH_SMEM);
    if (nblk < 1) nblk = 1;
    int grid = nsm * nblk;
    if (grid > 2 * NT) grid = 2 * NT;

    split_w_kernel<<<(2 * W1F4 + CWF4 + 255) / 256, 256>>>(w1, w2, fc1_w);
    conv_wmma_kernel<<<dim3(HW / 128, Bv), 256, CC_SMEM>>>(feature, fc1_b);
    sample_pool_kernel<<<dim3(Lv, Bv), 128>>>(lines);
    gemm_fused_kernel<<<grid, 128, GH_SMEM>>>(b1, b2, w3);
    head2_kernel<<<(NLINES + 255) / 256, 256>>>(b3);
    select_kernel<<<Bv, 1024>>>(lines, out);
}